// round 8
// baseline (speedup 1.0000x reference)
#include <cuda_runtime.h>
#include <math.h>
#include <stdint.h>

#define B_  32
#define TZ_ 16
#define TU_ 128
#define E_  512
#define H_  1024
#define V_  32000
#define XD_ (E_ + 2*H_)     // 2560
#define LN_EPS_ 1e-3f
#define FREQ_ 4
#define GEN_CTAS (V_/64)    // 500

// ---------------- scratch (device global, no allocs) ----------------
#define OFF_SCPU   0                          // (TU*B) x 8 score partials (u)
#define OFF_SCPZ   (OFF_SCPU + TU_*B_*8)      // (TZ*B) x 8
#define OFF_PHPU   (OFF_SCPZ + TZ_*B_*8)      // 8 x B x H
#define OFF_PHPZ   (OFF_PHPU + 8*B_*H_)       // 8 x B x H
#define OFF_X      (OFF_PHPZ + 8*B_*H_)       // B x 2560
#define OFF_PGI    (OFF_X + B_*XD_)           // 8 x B x 3H
#define OFF_PGH    (OFF_PGI + 8*B_*3*H_)      // 4 x B x 3H
#define OFF_GRU    (OFF_PGH + 4*B_*3*H_)      // B x H
#define OFF_GEN    (OFF_GRU + B_*H_)          // B x V
#define OFF_PGP    (OFF_GEN + B_*V_)          // 8 x B x H
#define OFF_ZCLIN  (OFF_PGP + 8*B_*H_)        // TZ*B x H
#define OFF_ZC     (OFF_ZCLIN + TZ_*B_*H_)    // B x TZ
#define OFF_MX     (OFF_ZC + B_*TZ_)
#define OFF_IS     (OFF_MX + B_)
#define OFF_CP     (OFF_IS + B_)
#define OFF_PMAX   (OFF_CP + B_*TZ_)          // GEN_CTAS x B
#define OFF_PSUM   (OFF_PMAX + GEN_CTAS*B_)
#define SCRATCH_TOTAL (OFF_PSUM + GEN_CTAS*B_)

__device__ float g_scratch[SCRATCH_TOTAL];

// ---------------- helpers ----------------
__device__ __forceinline__ uint32_t f2tf32u(float f) {
    uint32_t u;
    asm("cvt.rna.tf32.f32 %0, %1;" : "=r"(u) : "f"(f));
    return u;
}
__device__ __forceinline__ void cp16(void* smem, const void* gmem) {
    uint32_t s = (uint32_t)__cvta_generic_to_shared(smem);
    asm volatile("cp.async.ca.shared.global [%0], [%1], 16;" :: "r"(s), "l"(gmem));
}
__device__ __forceinline__ void cp_commit() { asm volatile("cp.async.commit_group;"); }
template<int N> __device__ __forceinline__ void cp_wait() {
    asm volatile("cp.async.wait_group %0;" :: "n"(N));
}

__device__ __forceinline__ float warpSum(float v) {
    #pragma unroll
    for (int o = 16; o; o >>= 1) v += __shfl_down_sync(0xffffffffu, v, o);
    return v;
}
__device__ float blockSum(float v) {
    __shared__ float sh[32];
    int lane = threadIdx.x & 31, wid = threadIdx.x >> 5;
    v = warpSum(v);
    if (lane == 0) sh[wid] = v;
    __syncthreads();
    v = (threadIdx.x < (blockDim.x >> 5)) ? sh[lane] : 0.f;
    if (wid == 0) v = warpSum(v);
    __syncthreads();
    return v;
}

// online softmax combine
__device__ __forceinline__ void osm(float& m, float& s, float m2, float s2) {
    float mn = fmaxf(m, m2);
    s = s * expf(m - mn) + s2 * expf(m2 - mn);
    m = mn;
}

// ---------------- tf32 tensor-core GEMM, multi-stage cp.async, BK=32 ----------------
// C[M,N] = A[M,K] @ op(B)
// TRANSB=false: B is KxN row-major; true: B is NxK (C = A@B^T)
// Split-K via grid.z (chunks of kLen; slice -> C + z*M*N)
// MODE 0: plain store (+bias if non-null)
// MODE 1: NO store; pre-reduce hp slices to smem; score partials:
//         scPart[(bm+row)*gridDim.x + bx] = sum_col v[col]*tanh(acc + hp[b][col] + ba[col])
// MODE 2: store (+bias) AND per-CTA online-softmax partials pmax/psum[bx*B_+row] (BM==32)
template<int BM,int BN,int BK,int WARPS_M,int WARPS_N,bool TRANSB,int STAGES,int MODE>
__global__ __launch_bounds__(32*WARPS_M*WARPS_N)
void gemm_k(const float* __restrict__ A, const float* __restrict__ Bm,
            const float* __restrict__ bias, float* __restrict__ C,
            int M, int N, int K, int kLen,
            const float* __restrict__ hpP, int hpS,
            const float* __restrict__ ba, const float* __restrict__ vv,
            float* __restrict__ scPart, float* __restrict__ pmax, float* __restrict__ psum)
{
    constexpr int NT  = 32 * WARPS_M * WARPS_N;
    constexpr int WM  = BM / WARPS_M;
    constexpr int WN  = BN / WARPS_N;
    constexpr int MT  = WM / 16;
    constexpr int NTL = WN / 8;
    constexpr int AST = BK + 4;
    constexpr int BROWS = TRANSB ? BN : BK;
    constexpr int BST   = TRANSB ? (BK + 4) : (BN + 8);

    extern __shared__ float sm_[];
    float* As_ = sm_;
    float* Bs_ = sm_ + STAGES * BM * AST;

    const int tid = threadIdx.x;
    const int wid = tid >> 5, lane = tid & 31;
    const int wm = wid / WARPS_N, wn = wid % WARPS_N;
    const int g = lane >> 2, tg = lane & 3;
    const int bm = blockIdx.y * BM, bn = blockIdx.x * BN;
    const int kStart = blockIdx.z * kLen;
    const int kTiles = kLen / BK;

    float acc[MT][NTL][4] = {};

    auto loadStage = [&](int s, int kb) {
        #pragma unroll
        for (int i = tid; i < BM * BK / 4; i += NT) {
            int r = i / (BK / 4), cq = i % (BK / 4);
            cp16(&As_[(s * BM + r) * AST + cq * 4],
                 &A[(size_t)(bm + r) * K + kStart + kb + cq * 4]);
        }
        if (!TRANSB) {
            #pragma unroll
            for (int i = tid; i < BK * BN / 4; i += NT) {
                int r = i / (BN / 4), cq = i % (BN / 4);
                cp16(&Bs_[(s * BROWS + r) * BST + cq * 4],
                     &Bm[(size_t)(kStart + kb + r) * N + bn + cq * 4]);
            }
        } else {
            #pragma unroll
            for (int i = tid; i < BN * BK / 4; i += NT) {
                int n = i / (BK / 4), cq = i % (BK / 4);
                cp16(&Bs_[(s * BROWS + n) * BST + cq * 4],
                     &Bm[(size_t)(bn + n) * K + kStart + kb + cq * 4]);
            }
        }
        cp_commit();
    };

    #pragma unroll
    for (int st = 0; st < STAGES - 1; st++) {
        if (st < kTiles) loadStage(st, st * BK); else cp_commit();
    }

    for (int kt = 0; kt < kTiles; kt++) {
        cp_wait<STAGES - 2>();
        __syncthreads();
        const int cur = kt % STAGES;
        const float* Asl = As_ + cur * BM * AST;
        const float* Bsl = Bs_ + cur * BROWS * BST;

        #pragma unroll
        for (int kk = 0; kk < BK; kk += 8) {
            uint32_t af[MT][4], bf[NTL][2];
            #pragma unroll
            for (int mt = 0; mt < MT; mt++) {
                int r0 = wm * WM + mt * 16 + g;
                af[mt][0] = f2tf32u(Asl[(r0    ) * AST + kk + tg    ]);
                af[mt][1] = f2tf32u(Asl[(r0 + 8) * AST + kk + tg    ]);
                af[mt][2] = f2tf32u(Asl[(r0    ) * AST + kk + tg + 4]);
                af[mt][3] = f2tf32u(Asl[(r0 + 8) * AST + kk + tg + 4]);
            }
            #pragma unroll
            for (int nt = 0; nt < NTL; nt++) {
                int c = wn * WN + nt * 8 + g;
                float b0 = TRANSB ? Bsl[c * BST + kk + tg    ] : Bsl[(kk + tg    ) * BST + c];
                float b1 = TRANSB ? Bsl[c * BST + kk + tg + 4] : Bsl[(kk + tg + 4) * BST + c];
                bf[nt][0] = f2tf32u(b0);
                bf[nt][1] = f2tf32u(b1);
            }
            #pragma unroll
            for (int mt = 0; mt < MT; mt++)
                #pragma unroll
                for (int nt = 0; nt < NTL; nt++) {
                    asm volatile(
                        "mma.sync.aligned.m16n8k8.row.col.f32.tf32.tf32.f32 "
                        "{%0,%1,%2,%3}, {%4,%5,%6,%7}, {%8,%9}, {%0,%1,%2,%3};\n"
                        : "+f"(acc[mt][nt][0]), "+f"(acc[mt][nt][1]),
                          "+f"(acc[mt][nt][2]), "+f"(acc[mt][nt][3])
                        : "r"(af[mt][0]), "r"(af[mt][1]), "r"(af[mt][2]), "r"(af[mt][3]),
                          "r"(bf[nt][0]), "r"(bf[nt][1]));
                }
        }
        __syncthreads();
        int nk = kt + STAGES - 1;
        if (nk < kTiles) loadStage(nk % STAGES, nk * BK); else cp_commit();
    }

    if constexpr (MODE == 0 || MODE == 2) {
        float* Cout = C + (size_t)blockIdx.z * M * N;
        float cv[MT][NTL][4];
        #pragma unroll
        for (int mt = 0; mt < MT; mt++) {
            int row0 = bm + wm * WM + mt * 16 + g;
            #pragma unroll
            for (int nt = 0; nt < NTL; nt++) {
                int col = bn + wn * WN + nt * 8 + 2 * tg;
                float bv0 = bias ? bias[col]     : 0.f;
                float bv1 = bias ? bias[col + 1] : 0.f;
                cv[mt][nt][0] = acc[mt][nt][0] + bv0;
                cv[mt][nt][1] = acc[mt][nt][1] + bv1;
                cv[mt][nt][2] = acc[mt][nt][2] + bv0;
                cv[mt][nt][3] = acc[mt][nt][3] + bv1;
                Cout[(size_t)row0 * N + col]           = cv[mt][nt][0];
                Cout[(size_t)row0 * N + col + 1]       = cv[mt][nt][1];
                Cout[(size_t)(row0 + 8) * N + col]     = cv[mt][nt][2];
                Cout[(size_t)(row0 + 8) * N + col + 1] = cv[mt][nt][3];
            }
        }
        if constexpr (MODE == 2) {
            __shared__ float smx[WARPS_N][32], ssm[WARPS_N][32], gmx[32];
            float lm[MT][2];
            #pragma unroll
            for (int mt = 0; mt < MT; mt++) {
                lm[mt][0] = -1e30f; lm[mt][1] = -1e30f;
                #pragma unroll
                for (int nt = 0; nt < NTL; nt++) {
                    lm[mt][0] = fmaxf(lm[mt][0], fmaxf(cv[mt][nt][0], cv[mt][nt][1]));
                    lm[mt][1] = fmaxf(lm[mt][1], fmaxf(cv[mt][nt][2], cv[mt][nt][3]));
                }
                #pragma unroll
                for (int h = 0; h < 2; h++) {
                    float m = lm[mt][h];
                    m = fmaxf(m, __shfl_xor_sync(0xffffffffu, m, 1));
                    m = fmaxf(m, __shfl_xor_sync(0xffffffffu, m, 2));
                    lm[mt][h] = m;
                    if (tg == 0) smx[wn][mt * 16 + h * 8 + g] = m;
                }
            }
            __syncthreads();
            if (tid < 32) {
                float m = smx[0][tid];
                #pragma unroll
                for (int w = 1; w < WARPS_N; w++) m = fmaxf(m, smx[w][tid]);
                gmx[tid] = m;
            }
            __syncthreads();
            #pragma unroll
            for (int mt = 0; mt < MT; mt++) {
                #pragma unroll
                for (int h = 0; h < 2; h++) {
                    int row = mt * 16 + h * 8 + g;
                    float m = gmx[row];
                    float s = 0.f;
                    #pragma unroll
                    for (int nt = 0; nt < NTL; nt++) {
                        s += expf(cv[mt][nt][2 * h]     - m);
                        s += expf(cv[mt][nt][2 * h + 1] - m);
                    }
                    s += __shfl_xor_sync(0xffffffffu, s, 1);
                    s += __shfl_xor_sync(0xffffffffu, s, 2);
                    if (tg == 0) ssm[wn][row] = s;
                }
            }
            __syncthreads();
            if (tid < 32) {
                float s = 0.f;
                #pragma unroll
                for (int w = 0; w < WARPS_N; w++) s += ssm[w][tid];
                pmax[(size_t)blockIdx.x * B_ + tid] = gmx[tid];
                psum[(size_t)blockIdx.x * B_ + tid] = s;
            }
        }
    }
    if constexpr (MODE == 1) {
        // pre-reduce hp slices into smem once per CTA
        __shared__ float hps[B_][BN + 4];
        for (int i = tid; i < B_ * BN; i += NT) {
            int b = i / BN, c = i % BN;
            float v = 0.f;
            for (int sl = 0; sl < hpS; sl++)
                v += hpP[(size_t)sl * B_ * H_ + (size_t)b * H_ + bn + c];
            hps[b][c] = v;
        }
        __shared__ float sred[WARPS_N][BM];
        __syncthreads();
        #pragma unroll
        for (int mt = 0; mt < MT; mt++) {
            int rloc0 = wm * WM + mt * 16 + g;
            #pragma unroll
            for (int h = 0; h < 2; h++) {
                int rloc = rloc0 + h * 8;
                int b = (bm + rloc) & (B_ - 1);
                float s = 0.f;
                #pragma unroll
                for (int nt = 0; nt < NTL; nt++) {
                    #pragma unroll
                    for (int j = 0; j < 2; j++) {
                        int cl = wn * WN + nt * 8 + 2 * tg + j;
                        float e = tanhf(acc[mt][nt][2 * h + j] + hps[b][cl] + ba[bn + cl]);
                        s += e * vv[bn + cl];
                    }
                }
                s += __shfl_xor_sync(0xffffffffu, s, 1);
                s += __shfl_xor_sync(0xffffffffu, s, 2);
                if (tg == 0) sred[wn][rloc] = s;
            }
        }
        __syncthreads();
        if (tid < BM) {
            float s = 0.f;
            #pragma unroll
            for (int w = 0; w < WARPS_N; w++) s += sred[w][tid];
            scPart[(size_t)(bm + tid) * gridDim.x + blockIdx.x] = s;
        }
    }
}

// dynamic smem sizes (BK=32, 3 stages)
#define BIG_SMEM  ((3*128*36 + 3*32*136) * 4)          // 107520
#define SK_SMEM   ((3*32*36 + 3*64*36) * 4)            // 41472

// ---------------- streams & events ----------------
static cudaStream_t g_s1, g_s2, g_s3;
static cudaEvent_t  g_evF, g_e1, g_e2, g_e3, g_eG, g_e4;
namespace {
struct SInit {
    SInit() {
        cudaStreamCreateWithFlags(&g_s1, cudaStreamNonBlocking);
        cudaStreamCreateWithFlags(&g_s2, cudaStreamNonBlocking);
        cudaStreamCreateWithFlags(&g_s3, cudaStreamNonBlocking);
        cudaEventCreateWithFlags(&g_evF, cudaEventDisableTiming);
        cudaEventCreateWithFlags(&g_e1,  cudaEventDisableTiming);
        cudaEventCreateWithFlags(&g_e2,  cudaEventDisableTiming);
        cudaEventCreateWithFlags(&g_e3,  cudaEventDisableTiming);
        cudaEventCreateWithFlags(&g_eG,  cudaEventDisableTiming);
        cudaEventCreateWithFlags(&g_e4,  cudaEventDisableTiming);
        cudaFuncSetAttribute((const void*)gemm_k<128,128,32,2,2,false,3,0>,
                             cudaFuncAttributeMaxDynamicSharedMemorySize, BIG_SMEM);
        cudaFuncSetAttribute((const void*)gemm_k<128,128,32,2,2,false,3,1>,
                             cudaFuncAttributeMaxDynamicSharedMemorySize, BIG_SMEM);
    }
};
SInit g_sinit;
}

// ---------------- embedding gather into x[:, 2H:2H+E] ----------------
__global__ void k_emb(const float* __restrict__ emb, const int* __restrict__ mt,
                      float* __restrict__ x)
{
    int b = blockIdx.x;
    int tok = mt[b];
    for (int e = threadIdx.x; e < E_; e += blockDim.x)
        x[b * XD_ + 2 * H_ + e] = emb[(size_t)tok * E_ + e];
}

// ---------------- softmax over t (from score partials) + context ----------------
__global__ void k_softmax_ctx(const float* __restrict__ scPart, int GX,
                              const float* __restrict__ enc,
                              float* __restrict__ x, int T, int xoff)
{
    int b = blockIdx.x;
    int h = blockIdx.y * 256 + threadIdx.x;
    int tid = threadIdx.x, lane = tid & 31, wid = tid >> 5;
    __shared__ float w[TU_];
    __shared__ float red[8];
    __shared__ float bval;
    float val = -1e30f;
    if (tid < T) {
        float s = 0.f;
        for (int gx = 0; gx < GX; gx++)
            s += scPart[(size_t)(tid * B_ + b) * GX + gx];
        w[tid] = s;
        val = s;
    }
    float m = val;
    #pragma unroll
    for (int o = 16; o; o >>= 1) m = fmaxf(m, __shfl_xor_sync(0xffffffffu, m, o));
    if (lane == 0) red[wid] = m;
    __syncthreads();
    if (tid == 0) {
        float mm = red[0];
        for (int i = 1; i < 8; i++) mm = fmaxf(mm, red[i]);
        bval = mm;
    }
    __syncthreads();
    float gmax = bval;
    float e = (tid < T) ? expf(w[tid] - gmax) : 0.f;
    float s = e;
    #pragma unroll
    for (int o = 16; o; o >>= 1) s += __shfl_xor_sync(0xffffffffu, s, o);
    if (lane == 0) red[wid] = s;
    __syncthreads();
    if (tid == 0) {
        float ss = 0.f;
        for (int i = 0; i < 8; i++) ss += red[i];
        bval = 1.f / ss;
    }
    __syncthreads();
    if (tid < T) w[tid] = e * bval;
    __syncthreads();
    float acc = 0.f;
    for (int t = 0; t < T; t++)
        acc += w[t] * enc[((size_t)t * B_ + b) * H_ + h];
    x[b * XD_ + xoff + h] = acc;
}

// ---------------- GRU cell + layernorm, reads split-K partial slices ----------------
__global__ void k_gru_ln(const float* __restrict__ Pgi, int nsi,
                         const float* __restrict__ Pgh, int nsh,
                         const float* __restrict__ b_ih, const float* __restrict__ b_hh,
                         const float* __restrict__ hprev,
                         const float* __restrict__ la, const float* __restrict__ lb,
                         float* __restrict__ gru_out, float* __restrict__ hnew_out)
{
    int b = blockIdx.x;
    __shared__ float hn[H_];
    __shared__ float mu_s, sig_s;
    const size_t SL = (size_t)B_ * 3 * H_;
    for (int h = threadIdx.x; h < H_; h += blockDim.x) {
        float ir = b_ih[h], iz = b_ih[H_ + h], in = b_ih[2 * H_ + h];
        for (int s = 0; s < nsi; s++) {
            const float* p = Pgi + s * SL + (size_t)b * 3 * H_;
            ir += p[h]; iz += p[H_ + h]; in += p[2 * H_ + h];
        }
        float hr = b_hh[h], hz = b_hh[H_ + h], hnn = b_hh[2 * H_ + h];
        for (int s = 0; s < nsh; s++) {
            const float* p = Pgh + s * SL + (size_t)b * 3 * H_;
            hr += p[h]; hz += p[H_ + h]; hnn += p[2 * H_ + h];
        }
        float r  = 1.f / (1.f + expf(-(ir + hr)));
        float zg = 1.f / (1.f + expf(-(iz + hz)));
        float n  = tanhf(in + r * hnn);
        float hp = hprev[b * H_ + h];
        hn[h] = (1.f - zg) * n + zg * hp;
    }
    __syncthreads();
    float s = 0.f;
    for (int h = threadIdx.x; h < H_; h += blockDim.x) s += hn[h];
    s = blockSum(s);
    if (threadIdx.x == 0) mu_s = s / H_;
    __syncthreads();
    float mu = mu_s;
    float vs = 0.f;
    for (int h = threadIdx.x; h < H_; h += blockDim.x) { float d = hn[h] - mu; vs += d * d; }
    vs = blockSum(vs);
    if (threadIdx.x == 0) sig_s = sqrtf(vs / (float)(H_ - 1));
    __syncthreads();
    float inv = 1.f / (sig_s + LN_EPS_);
    for (int h = threadIdx.x; h < H_; h += blockDim.x) {
        gru_out[b * H_ + h] = (hn[h] - mu) * inv * la[h] + lb[h];
        hnew_out[b * H_ + h] = hn[h];
    }
}

// ---------------- copy-attention scores (reads gpart partial slices) ----------------
__global__ void k_zc(const float* __restrict__ zclin, const float* __restrict__ Pgp, int nsp,
                     const float* __restrict__ bc, const float* __restrict__ Wv1,
                     const float* __restrict__ bv1, float* __restrict__ zc)
{
    int tb = blockIdx.x;
    int t = tb / B_, b = tb % B_;
    float s = 0.f;
    for (int h = threadIdx.x; h < H_; h += blockDim.x) {
        float gp = 0.f;
        for (int sl = 0; sl < nsp; sl++)
            gp += Pgp[(size_t)sl * B_ * H_ + (size_t)b * H_ + h];
        s += Wv1[h] * tanhf(zclin[(size_t)tb * H_ + h] + gp + bc[h]);
    }
    s = blockSum(s);
    if (threadIdx.x == 0) zc[b * TZ_ + t] = s + bv1[0];
}

// ---------------- combine per-CTA softmax partials + zc ----------------
__global__ void k_stats(const float* __restrict__ pmax, const float* __restrict__ psum,
                        const float* __restrict__ zc,
                        float* __restrict__ mx, float* __restrict__ invs,
                        float* __restrict__ cp)
{
    int b = blockIdx.x, tid = threadIdx.x;
    int lane = tid & 31, wid = tid >> 5;
    float m = -1e30f, s = 0.f;
    for (int i = tid; i < GEN_CTAS; i += blockDim.x)
        osm(m, s, pmax[(size_t)i * B_ + b], psum[(size_t)i * B_ + b]);
    if (tid < TZ_) osm(m, s, zc[b * TZ_ + tid], 1.f);
    #pragma unroll
    for (int o = 16; o; o >>= 1) {
        float m2 = __shfl_xor_sync(0xffffffffu, m, o);
        float s2 = __shfl_xor_sync(0xffffffffu, s, o);
        osm(m, s, m2, s2);
    }
    __shared__ float shm[8], shs[8];
    __shared__ float fm, fs;
    if (lane == 0) { shm[wid] = m; shs[wid] = s; }
    __syncthreads();
    if (tid == 0) {
        float M = shm[0], S = shs[0];
        for (int w = 1; w < 8; w++) osm(M, S, shm[w], shs[w]);
        fm = M; fs = S;
        mx[b] = M; invs[b] = 1.f / S;
    }
    __syncthreads();
    if (tid < TZ_) cp[b * TZ_ + tid] = expf(zc[b * TZ_ + tid] - fm) / fs;
}

// ---------------- final: proba = gen_p + mask * (copy_p @ pz_proba), float4 ----------------
__global__ void k_write(const float* __restrict__ gen, const float* __restrict__ pz,
                        const float* __restrict__ mx, const float* __restrict__ invs,
                        const float* __restrict__ cp, float* __restrict__ out)
{
    int idx = blockIdx.x * blockDim.x + threadIdx.x;   // float4 index
    if (idx >= B_ * V_ / 4) return;
    int b = idx / (V_ / 4), v4 = idx % (V_ / 4);
    float4 g = ((const float4*)gen)[idx];
    float m = mx[b], inv = invs[b];
    float4 o;
    o.x = expf(g.x - m) * inv;
    o.y = expf(g.y - m) * inv;
    o.z = expf(g.z - m) * inv;
    o.w = expf(g.w - m) * inv;
    if (v4 >= FREQ_ / 4) {   // v >= 4 for all lanes of this float4
        float cx = 0.f, cy = 0.f, cz = 0.f, cw = 0.f;
        #pragma unroll
        for (int t = 0; t < TZ_; t++) {
            float w = cp[b * TZ_ + t];
            float4 p = ((const float4*)(pz + ((size_t)t * B_ + b) * V_))[v4];
            cx += w * p.x; cy += w * p.y; cz += w * p.z; cw += w * p.w;
        }
        o.x += cx; o.y += cy; o.z += cz; o.w += cw;
    }
    ((float4*)out)[idx] = o;
}

// ---------------- launch ----------------
extern "C" void kernel_launch(void* const* d_in, const int* in_sizes, int n_in,
                              void* d_out, int out_size)
{
    const float* z_enc  = (const float*)d_in[0];
    const float* pz     = (const float*)d_in[1];
    const float* u_enc  = (const float*)d_in[2];
    const int*   mt     = (const int*)  d_in[3];
    const float* hid    = (const float*)d_in[4];
    const float* emb    = (const float*)d_in[5];
    const float* Wa_z   = (const float*)d_in[6];
    const float* ba_z   = (const float*)d_in[7];
    const float* v_z    = (const float*)d_in[8];
    const float* Wa_u   = (const float*)d_in[9];
    const float* ba_u   = (const float*)d_in[10];
    const float* v_u    = (const float*)d_in[11];
    const float* W_ih   = (const float*)d_in[12];
    const float* W_hh   = (const float*)d_in[13];
    const float* b_ih   = (const float*)d_in[14];
    const float* b_hh   = (const float*)d_in[15];
    const float* ln_a   = (const float*)d_in[16];
    const float* ln_b   = (const float*)d_in[17];
    const float* W_proj = (const float*)d_in[18];
    const float* b_proj = (const float*)d_in[19];
    const float* W_c    = (const float*)d_in[20];
    const float* b_c    = (const float*)d_in[21];
    const float* W_v1   = (const float*)d_in[22];
    const float* b_v1   = (const float*)d_in[23];
    float* out = (float*)d_out;

    float* S;
    cudaGetSymbolAddress((void**)&S, g_scratch);
    float* scpU  = S + OFF_SCPU;
    float* scpZ  = S + OFF_SCPZ;
    float* PhpU  = S + OFF_PHPU;
    float* PhpZ  = S + OFF_PHPZ;
    float* x     = S + OFF_X;
    float* Pgi   = S + OFF_PGI;
    float* Pgh   = S + OFF_PGH;
    float* gru   = S + OFF_GRU;
    float* gen   = S + OFF_GEN;
    float* Pgp   = S + OFF_PGP;
    float* zclin = S + OFF_ZCLIN;
    float* zc    = S + OFF_ZC;
    float* mx    = S + OFF_MX;
    float* invs  = S + OFF_IS;
    float* cp    = S + OFF_CP;
    float* pmax  = S + OFF_PMAX;
    float* psum  = S + OFF_PSUM;

    // ---------- fork ----------
    cudaEventRecord(g_evF, 0);
    cudaStreamWaitEvent(g_s1, g_evF, 0);
    cudaStreamWaitEvent(g_s2, g_evF, 0);
    cudaStreamWaitEvent(g_s3, g_evF, 0);

    // s0: hp_u (split8) then Eu fused-score, ctx_u
    gemm_k<32,64,32,1,4,false,3,0><<<dim3(H_/64,1,8),128,SK_SMEM>>>(
        hid, Wa_u, nullptr, PhpU, B_, H_, H_, H_/8,
        nullptr,0,nullptr,nullptr,nullptr,nullptr,nullptr);
    gemm_k<128,128,32,2,2,false,3,1><<<dim3(H_/128, TU_*B_/128, 1),128,BIG_SMEM>>>(
        u_enc, Wa_u + (size_t)H_*H_, nullptr, nullptr, TU_*B_, H_, H_, H_,
        PhpU, 8, ba_u, v_u, scpU, nullptr, nullptr);
    k_softmax_ctx<<<dim3(B_, H_/256), 256>>>(scpU, H_/128, u_enc, x, TU_, H_);

    // s1: hp_z (split8), Ez fused-score, ctx_z
    gemm_k<32,64,32,1,4,false,3,0><<<dim3(H_/64,1,8),128,SK_SMEM,g_s1>>>(
        hid, Wa_z, nullptr, PhpZ, B_, H_, H_, H_/8,
        nullptr,0,nullptr,nullptr,nullptr,nullptr,nullptr);
    gemm_k<128,128,32,2,2,false,3,1><<<dim3(H_/128, TZ_*B_/128, 1),128,BIG_SMEM,g_s1>>>(
        z_enc, Wa_z + (size_t)H_*H_, nullptr, nullptr, TZ_*B_, H_, H_, H_,
        PhpZ, 8, ba_z, v_z, scpZ, nullptr, nullptr);
    k_softmax_ctx<<<dim3(B_, H_/256), 256, 0, g_s1>>>(scpZ, H_/128, z_enc, x, TZ_, 0);
    cudaEventRecord(g_e1, g_s1);

    // s2: emb + gh (split4, partials consumed by gru)
    k_emb<<<B_, 128, 0, g_s2>>>(emb, mt, x);
    gemm_k<32,64,32,1,4,true,3,0><<<dim3(3*H_/64,1,4),128,SK_SMEM,g_s2>>>(
        hid, W_hh, nullptr, Pgh, B_, 3*H_, H_, H_/4,
        nullptr,0,nullptr,nullptr,nullptr,nullptr,nullptr);
    cudaEventRecord(g_e2, g_s2);

    // s3: zclin
    gemm_k<128,128,32,2,2,false,3,0><<<dim3(H_/128, TZ_*B_/128, 1),128,BIG_SMEM,g_s3>>>(
        z_enc, W_c, nullptr, zclin, TZ_*B_, H_, H_, H_,
        nullptr,0,nullptr,nullptr,nullptr,nullptr,nullptr);
    cudaEventRecord(g_e3, g_s3);

    // ---------- join for gi ----------
    cudaStreamWaitEvent(0, g_e1, 0);
    cudaStreamWaitEvent(0, g_e2, 0);
    gemm_k<32,64,32,1,4,true,3,0><<<dim3(3*H_/64,1,8),128,SK_SMEM>>>(
        x, W_ih, nullptr, Pgi, B_, 3*H_, XD_, XD_/8,
        nullptr,0,nullptr,nullptr,nullptr,nullptr,nullptr);
    k_gru_ln<<<B_, 256>>>(Pgi, 8, Pgh, 4, b_ih, b_hh, hid, ln_a, ln_b,
                          gru, out + (size_t)B_ * V_);

    // ---------- fork 2: copy path ∥ vocab GEMM ----------
    cudaEventRecord(g_eG, 0);
    cudaStreamWaitEvent(g_s1, g_eG, 0);
    cudaStreamWaitEvent(g_s1, g_e3, 0);
    gemm_k<32,64,32,1,4,false,3,0><<<dim3(H_/64,1,8),128,SK_SMEM,g_s1>>>(
        gru, W_c + (size_t)H_*H_, nullptr, Pgp, B_, H_, H_, H_/8,
        nullptr,0,nullptr,nullptr,nullptr,nullptr,nullptr);
    k_zc<<<TZ_ * B_, 256, 0, g_s1>>>(zclin, Pgp, 8, b_c, W_v1, b_v1, zc);
    cudaEventRecord(g_e4, g_s1);

    // s0: gen = gru @ W_proj + b_proj, with fused online-softmax partials
    gemm_k<32,64,32,1,4,false,3,2><<<dim3(V_/64,1,1),128,SK_SMEM>>>(
        gru, W_proj, b_proj, gen, B_, V_, H_, H_,
        nullptr,0,nullptr,nullptr,nullptr, pmax, psum);

    // ---------- join + final ----------
    cudaStreamWaitEvent(0, g_e4, 0);
    k_stats<<<B_, 256>>>(pmax, psum, zc, mx, invs, cp);
    k_write<<<(B_ * V_ / 4 + 255) / 256, 256>>>(gen, pz, mx, invs, cp, out);
}

// round 12
// speedup vs baseline: 1.1700x; 1.1700x over previous
#include <cuda_runtime.h>
#include <math.h>
#include <stdint.h>

#define B_  32
#define TZ_ 16
#define TU_ 128
#define E_  512
#define H_  1024
#define V_  32000
#define XD_ (E_ + 2*H_)     // 2560
#define LN_EPS_ 1e-3f
#define FREQ_ 4
#define GEN_CTAS (V_/64)    // 500

// ---------------- scratch (device global, no allocs) ----------------
#define OFF_SCPU   0                          // (TU*B) x 8 score partials (u)
#define OFF_SCPZ   (OFF_SCPU + TU_*B_*8)      // (TZ*B) x 8
#define OFF_PHPU   (OFF_SCPZ + TZ_*B_*8)      // 8 x B x H
#define OFF_PHPZ   (OFF_PHPU + 8*B_*H_)       // 8 x B x H
#define OFF_X      (OFF_PHPZ + 8*B_*H_)       // B x 2560
#define OFF_PGI    (OFF_X + B_*XD_)           // 8 x B x 3H (uses 5 slices)
#define OFF_PGH    (OFF_PGI + 8*B_*3*H_)      // 4 x B x 3H
#define OFF_GRU    (OFF_PGH + 4*B_*3*H_)      // B x H
#define OFF_GEN    (OFF_GRU + B_*H_)          // B x V
#define OFF_PGP    (OFF_GEN + B_*V_)          // 8 x B x H
#define OFF_ZCLIN  (OFF_PGP + 8*B_*H_)        // TZ*B x H
#define OFF_ZC     (OFF_ZCLIN + TZ_*B_*H_)    // B x TZ
#define OFF_MX     (OFF_ZC + B_*TZ_)
#define OFF_IS     (OFF_MX + B_)
#define OFF_CP     (OFF_IS + B_)
#define OFF_PMAX   (OFF_CP + B_*TZ_)          // GEN_CTAS x B
#define OFF_PSUM   (OFF_PMAX + GEN_CTAS*B_)
#define SCRATCH_TOTAL (OFF_PSUM + GEN_CTAS*B_)

__device__ float g_scratch[SCRATCH_TOTAL];

// ---------------- helpers ----------------
__device__ __forceinline__ uint32_t f2tf32u(float f) {
    uint32_t u;
    asm("cvt.rna.tf32.f32 %0, %1;" : "=r"(u) : "f"(f));
    return u;
}
__device__ __forceinline__ void cp16(void* smem, const void* gmem) {
    uint32_t s = (uint32_t)__cvta_generic_to_shared(smem);
    asm volatile("cp.async.ca.shared.global [%0], [%1], 16;" :: "r"(s), "l"(gmem));
}
__device__ __forceinline__ void cp_commit() { asm volatile("cp.async.commit_group;"); }
template<int N> __device__ __forceinline__ void cp_wait() {
    asm volatile("cp.async.wait_group %0;" :: "n"(N));
}

__device__ __forceinline__ float warpSum(float v) {
    #pragma unroll
    for (int o = 16; o; o >>= 1) v += __shfl_down_sync(0xffffffffu, v, o);
    return v;
}
__device__ float blockSum(float v) {
    __shared__ float sh[32];
    int lane = threadIdx.x & 31, wid = threadIdx.x >> 5;
    v = warpSum(v);
    if (lane == 0) sh[wid] = v;
    __syncthreads();
    v = (threadIdx.x < (blockDim.x >> 5)) ? sh[lane] : 0.f;
    if (wid == 0) v = warpSum(v);
    __syncthreads();
    return v;
}

// online softmax combine
__device__ __forceinline__ void osm(float& m, float& s, float m2, float s2) {
    float mn = fmaxf(m, m2);
    s = s * expf(m - mn) + s2 * expf(m2 - mn);
    m = mn;
}

// ---------------- tf32 tensor-core GEMM, multi-stage cp.async, BK=32 ----------------
// C[M,N] = A[M,K] @ op(B)   (K param is the LDA/LDB reduction stride; kLen per z-slice)
// TRANSB=false: B is KxN row-major; true: B is NxK (C = A@B^T)
// Split-K via grid.z (chunks of kLen; slice -> C + z*M*N)
// MODE 0: plain store (+bias if non-null)
// MODE 1: NO store; pre-reduce hp slices to smem; score partials:
//         scPart[(bm+row)*gridDim.x + bx] = sum_col v[col]*tanh(acc + hp[b][col] + ba[col])
// MODE 2: store (+bias) AND per-CTA online-softmax partials pmax/psum[bx*B_+row] (BM==32)
template<int BM,int BN,int BK,int WARPS_M,int WARPS_N,bool TRANSB,int STAGES,int MODE>
__global__ __launch_bounds__(32*WARPS_M*WARPS_N)
void gemm_k(const float* __restrict__ A, const float* __restrict__ Bm,
            const float* __restrict__ bias, float* __restrict__ C,
            int M, int N, int K, int kLen,
            const float* __restrict__ hpP, int hpS,
            const float* __restrict__ ba, const float* __restrict__ vv,
            float* __restrict__ scPart, float* __restrict__ pmax, float* __restrict__ psum)
{
    constexpr int NT  = 32 * WARPS_M * WARPS_N;
    constexpr int WM  = BM / WARPS_M;
    constexpr int WN  = BN / WARPS_N;
    constexpr int MT  = WM / 16;
    constexpr int NTL = WN / 8;
    constexpr int AST = BK + 4;
    constexpr int BROWS = TRANSB ? BN : BK;
    constexpr int BST   = TRANSB ? (BK + 4) : (BN + 8);

    extern __shared__ float sm_[];
    float* As_ = sm_;
    float* Bs_ = sm_ + STAGES * BM * AST;

    const int tid = threadIdx.x;
    const int wid = tid >> 5, lane = tid & 31;
    const int wm = wid / WARPS_N, wn = wid % WARPS_N;
    const int g = lane >> 2, tg = lane & 3;
    const int bm = blockIdx.y * BM, bn = blockIdx.x * BN;
    const int kStart = blockIdx.z * kLen;
    const int kTiles = kLen / BK;

    float acc[MT][NTL][4] = {};

    auto loadStage = [&](int s, int kb) {
        #pragma unroll
        for (int i = tid; i < BM * BK / 4; i += NT) {
            int r = i / (BK / 4), cq = i % (BK / 4);
            cp16(&As_[(s * BM + r) * AST + cq * 4],
                 &A[(size_t)(bm + r) * K + kStart + kb + cq * 4]);
        }
        if (!TRANSB) {
            #pragma unroll
            for (int i = tid; i < BK * BN / 4; i += NT) {
                int r = i / (BN / 4), cq = i % (BN / 4);
                cp16(&Bs_[(s * BROWS + r) * BST + cq * 4],
                     &Bm[(size_t)(kStart + kb + r) * N + bn + cq * 4]);
            }
        } else {
            #pragma unroll
            for (int i = tid; i < BN * BK / 4; i += NT) {
                int n = i / (BK / 4), cq = i % (BK / 4);
                cp16(&Bs_[(s * BROWS + n) * BST + cq * 4],
                     &Bm[(size_t)(bn + n) * K + kStart + kb + cq * 4]);
            }
        }
        cp_commit();
    };

    #pragma unroll
    for (int st = 0; st < STAGES - 1; st++) {
        if (st < kTiles) loadStage(st, st * BK); else cp_commit();
    }

    for (int kt = 0; kt < kTiles; kt++) {
        cp_wait<STAGES - 2>();
        __syncthreads();
        const int cur = kt % STAGES;
        const float* Asl = As_ + cur * BM * AST;
        const float* Bsl = Bs_ + cur * BROWS * BST;

        #pragma unroll
        for (int kk = 0; kk < BK; kk += 8) {
            uint32_t af[MT][4], bf[NTL][2];
            #pragma unroll
            for (int mt = 0; mt < MT; mt++) {
                int r0 = wm * WM + mt * 16 + g;
                af[mt][0] = f2tf32u(Asl[(r0    ) * AST + kk + tg    ]);
                af[mt][1] = f2tf32u(Asl[(r0 + 8) * AST + kk + tg    ]);
                af[mt][2] = f2tf32u(Asl[(r0    ) * AST + kk + tg + 4]);
                af[mt][3] = f2tf32u(Asl[(r0 + 8) * AST + kk + tg + 4]);
            }
            #pragma unroll
            for (int nt = 0; nt < NTL; nt++) {
                int c = wn * WN + nt * 8 + g;
                float b0 = TRANSB ? Bsl[c * BST + kk + tg    ] : Bsl[(kk + tg    ) * BST + c];
                float b1 = TRANSB ? Bsl[c * BST + kk + tg + 4] : Bsl[(kk + tg + 4) * BST + c];
                bf[nt][0] = f2tf32u(b0);
                bf[nt][1] = f2tf32u(b1);
            }
            #pragma unroll
            for (int mt = 0; mt < MT; mt++)
                #pragma unroll
                for (int nt = 0; nt < NTL; nt++) {
                    asm volatile(
                        "mma.sync.aligned.m16n8k8.row.col.f32.tf32.tf32.f32 "
                        "{%0,%1,%2,%3}, {%4,%5,%6,%7}, {%8,%9}, {%0,%1,%2,%3};\n"
                        : "+f"(acc[mt][nt][0]), "+f"(acc[mt][nt][1]),
                          "+f"(acc[mt][nt][2]), "+f"(acc[mt][nt][3])
                        : "r"(af[mt][0]), "r"(af[mt][1]), "r"(af[mt][2]), "r"(af[mt][3]),
                          "r"(bf[nt][0]), "r"(bf[nt][1]));
                }
        }
        __syncthreads();
        int nk = kt + STAGES - 1;
        if (nk < kTiles) loadStage(nk % STAGES, nk * BK); else cp_commit();
    }

    if constexpr (MODE == 0 || MODE == 2) {
        float* Cout = C + (size_t)blockIdx.z * M * N;
        float cv[MT][NTL][4];
        #pragma unroll
        for (int mt = 0; mt < MT; mt++) {
            int row0 = bm + wm * WM + mt * 16 + g;
            #pragma unroll
            for (int nt = 0; nt < NTL; nt++) {
                int col = bn + wn * WN + nt * 8 + 2 * tg;
                float bv0 = bias ? bias[col]     : 0.f;
                float bv1 = bias ? bias[col + 1] : 0.f;
                cv[mt][nt][0] = acc[mt][nt][0] + bv0;
                cv[mt][nt][1] = acc[mt][nt][1] + bv1;
                cv[mt][nt][2] = acc[mt][nt][2] + bv0;
                cv[mt][nt][3] = acc[mt][nt][3] + bv1;
                Cout[(size_t)row0 * N + col]           = cv[mt][nt][0];
                Cout[(size_t)row0 * N + col + 1]       = cv[mt][nt][1];
                Cout[(size_t)(row0 + 8) * N + col]     = cv[mt][nt][2];
                Cout[(size_t)(row0 + 8) * N + col + 1] = cv[mt][nt][3];
            }
        }
        if constexpr (MODE == 2) {
            __shared__ float smx[WARPS_N][32], ssm[WARPS_N][32], gmx[32];
            float lm[MT][2];
            #pragma unroll
            for (int mt = 0; mt < MT; mt++) {
                lm[mt][0] = -1e30f; lm[mt][1] = -1e30f;
                #pragma unroll
                for (int nt = 0; nt < NTL; nt++) {
                    lm[mt][0] = fmaxf(lm[mt][0], fmaxf(cv[mt][nt][0], cv[mt][nt][1]));
                    lm[mt][1] = fmaxf(lm[mt][1], fmaxf(cv[mt][nt][2], cv[mt][nt][3]));
                }
                #pragma unroll
                for (int h = 0; h < 2; h++) {
                    float m = lm[mt][h];
                    m = fmaxf(m, __shfl_xor_sync(0xffffffffu, m, 1));
                    m = fmaxf(m, __shfl_xor_sync(0xffffffffu, m, 2));
                    lm[mt][h] = m;
                    if (tg == 0) smx[wn][mt * 16 + h * 8 + g] = m;
                }
            }
            __syncthreads();
            if (tid < 32) {
                float m = smx[0][tid];
                #pragma unroll
                for (int w = 1; w < WARPS_N; w++) m = fmaxf(m, smx[w][tid]);
                gmx[tid] = m;
            }
            __syncthreads();
            #pragma unroll
            for (int mt = 0; mt < MT; mt++) {
                #pragma unroll
                for (int h = 0; h < 2; h++) {
                    int row = mt * 16 + h * 8 + g;
                    float m = gmx[row];
                    float s = 0.f;
                    #pragma unroll
                    for (int nt = 0; nt < NTL; nt++) {
                        s += expf(cv[mt][nt][2 * h]     - m);
                        s += expf(cv[mt][nt][2 * h + 1] - m);
                    }
                    s += __shfl_xor_sync(0xffffffffu, s, 1);
                    s += __shfl_xor_sync(0xffffffffu, s, 2);
                    if (tg == 0) ssm[wn][row] = s;
                }
            }
            __syncthreads();
            if (tid < 32) {
                float s = 0.f;
                #pragma unroll
                for (int w = 0; w < WARPS_N; w++) s += ssm[w][tid];
                pmax[(size_t)blockIdx.x * B_ + tid] = gmx[tid];
                psum[(size_t)blockIdx.x * B_ + tid] = s;
            }
        }
    }
    if constexpr (MODE == 1) {
        // pre-reduce hp slices into smem once per CTA
        __shared__ float hps[B_][BN + 4];
        for (int i = tid; i < B_ * BN; i += NT) {
            int b = i / BN, c = i % BN;
            float v = 0.f;
            for (int sl = 0; sl < hpS; sl++)
                v += hpP[(size_t)sl * B_ * H_ + (size_t)b * H_ + bn + c];
            hps[b][c] = v;
        }
        __shared__ float sred[WARPS_N][BM];
        __syncthreads();
        #pragma unroll
        for (int mt = 0; mt < MT; mt++) {
            int rloc0 = wm * WM + mt * 16 + g;
            #pragma unroll
            for (int h = 0; h < 2; h++) {
                int rloc = rloc0 + h * 8;
                int b = (bm + rloc) & (B_ - 1);
                float s = 0.f;
                #pragma unroll
                for (int nt = 0; nt < NTL; nt++) {
                    #pragma unroll
                    for (int j = 0; j < 2; j++) {
                        int cl = wn * WN + nt * 8 + 2 * tg + j;
                        float e = tanhf(acc[mt][nt][2 * h + j] + hps[b][cl] + ba[bn + cl]);
                        s += e * vv[bn + cl];
                    }
                }
                s += __shfl_xor_sync(0xffffffffu, s, 1);
                s += __shfl_xor_sync(0xffffffffu, s, 2);
                if (tg == 0) sred[wn][rloc] = s;
            }
        }
        __syncthreads();
        if (tid < BM) {
            float s = 0.f;
            #pragma unroll
            for (int w = 0; w < WARPS_N; w++) s += sred[w][tid];
            scPart[(size_t)(bm + tid) * gridDim.x + blockIdx.x] = s;
        }
    }
}

// dynamic smem sizes (BK=32, 3 stages)
#define BIG_SMEM  ((3*128*36 + 3*32*136) * 4)          // 107520
#define SK_SMEM   ((3*32*36 + 3*64*36) * 4)            // 41472

// ---------------- streams & events ----------------
static cudaStream_t g_s1, g_s2, g_s3;
static cudaEvent_t  g_evF, g_e1, g_e2, g_e3, g_eG, g_e4;
namespace {
struct SInit {
    SInit() {
        cudaStreamCreateWithFlags(&g_s1, cudaStreamNonBlocking);
        cudaStreamCreateWithFlags(&g_s2, cudaStreamNonBlocking);
        cudaStreamCreateWithFlags(&g_s3, cudaStreamNonBlocking);
        cudaEventCreateWithFlags(&g_evF, cudaEventDisableTiming);
        cudaEventCreateWithFlags(&g_e1,  cudaEventDisableTiming);
        cudaEventCreateWithFlags(&g_e2,  cudaEventDisableTiming);
        cudaEventCreateWithFlags(&g_e3,  cudaEventDisableTiming);
        cudaEventCreateWithFlags(&g_eG,  cudaEventDisableTiming);
        cudaEventCreateWithFlags(&g_e4,  cudaEventDisableTiming);
        cudaFuncSetAttribute((const void*)gemm_k<128,128,32,2,4,false,3,0>,
                             cudaFuncAttributeMaxDynamicSharedMemorySize, BIG_SMEM);
        cudaFuncSetAttribute((const void*)gemm_k<128,128,32,2,4,false,3,1>,
                             cudaFuncAttributeMaxDynamicSharedMemorySize, BIG_SMEM);
    }
};
SInit g_sinit;
}

// ---------------- embedding gather into x[:, 2H:2H+E] ----------------
__global__ void k_emb(const float* __restrict__ emb, const int* __restrict__ mt,
                      float* __restrict__ x)
{
    int b = blockIdx.x;
    int tok = mt[b];
    for (int e = threadIdx.x; e < E_; e += blockDim.x)
        x[b * XD_ + 2 * H_ + e] = emb[(size_t)tok * E_ + e];
}

// ---------------- softmax over t (from score partials) + context ----------------
__global__ void k_softmax_ctx(const float* __restrict__ scPart, int GX,
                              const float* __restrict__ enc,
                              float* __restrict__ x, int T, int xoff)
{
    int b = blockIdx.x;
    int h = blockIdx.y * 256 + threadIdx.x;
    int tid = threadIdx.x, lane = tid & 31, wid = tid >> 5;
    __shared__ float w[TU_];
    __shared__ float red[8];
    __shared__ float bval;
    float val = -1e30f;
    if (tid < T) {
        float s = 0.f;
        for (int gx = 0; gx < GX; gx++)
            s += scPart[(size_t)(tid * B_ + b) * GX + gx];
        w[tid] = s;
        val = s;
    }
    float m = val;
    #pragma unroll
    for (int o = 16; o; o >>= 1) m = fmaxf(m, __shfl_xor_sync(0xffffffffu, m, o));
    if (lane == 0) red[wid] = m;
    __syncthreads();
    if (tid == 0) {
        float mm = red[0];
        for (int i = 1; i < 8; i++) mm = fmaxf(mm, red[i]);
        bval = mm;
    }
    __syncthreads();
    float gmax = bval;
    float e = (tid < T) ? expf(w[tid] - gmax) : 0.f;
    float s = e;
    #pragma unroll
    for (int o = 16; o; o >>= 1) s += __shfl_xor_sync(0xffffffffu, s, o);
    if (lane == 0) red[wid] = s;
    __syncthreads();
    if (tid == 0) {
        float ss = 0.f;
        for (int i = 0; i < 8; i++) ss += red[i];
        bval = 1.f / ss;
    }
    __syncthreads();
    if (tid < T) w[tid] = e * bval;
    __syncthreads();
    float acc = 0.f;
    for (int t = 0; t < T; t++)
        acc += w[t] * enc[((size_t)t * B_ + b) * H_ + h];
    x[b * XD_ + xoff + h] = acc;
}

// ---------------- GRU cell + layernorm, reads split-K partial slices ----------------
__global__ void k_gru_ln(const float* __restrict__ Pgi, int nsi,
                         const float* __restrict__ Pgh, int nsh,
                         const float* __restrict__ b_ih, const float* __restrict__ b_hh,
                         const float* __restrict__ hprev,
                         const float* __restrict__ la, const float* __restrict__ lb,
                         float* __restrict__ gru_out, float* __restrict__ hnew_out)
{
    int b = blockIdx.x;
    __shared__ float hn[H_];
    __shared__ float mu_s, sig_s;
    const size_t SL = (size_t)B_ * 3 * H_;
    for (int h = threadIdx.x; h < H_; h += blockDim.x) {
        float ir = b_ih[h], iz = b_ih[H_ + h], in = b_ih[2 * H_ + h];
        for (int s = 0; s < nsi; s++) {
            const float* p = Pgi + s * SL + (size_t)b * 3 * H_;
            ir += p[h]; iz += p[H_ + h]; in += p[2 * H_ + h];
        }
        float hr = b_hh[h], hz = b_hh[H_ + h], hnn = b_hh[2 * H_ + h];
        for (int s = 0; s < nsh; s++) {
            const float* p = Pgh + s * SL + (size_t)b * 3 * H_;
            hr += p[h]; hz += p[H_ + h]; hnn += p[2 * H_ + h];
        }
        float r  = 1.f / (1.f + expf(-(ir + hr)));
        float zg = 1.f / (1.f + expf(-(iz + hz)));
        float n  = tanhf(in + r * hnn);
        float hp = hprev[b * H_ + h];
        hn[h] = (1.f - zg) * n + zg * hp;
    }
    __syncthreads();
    float s = 0.f;
    for (int h = threadIdx.x; h < H_; h += blockDim.x) s += hn[h];
    s = blockSum(s);
    if (threadIdx.x == 0) mu_s = s / H_;
    __syncthreads();
    float mu = mu_s;
    float vs = 0.f;
    for (int h = threadIdx.x; h < H_; h += blockDim.x) { float d = hn[h] - mu; vs += d * d; }
    vs = blockSum(vs);
    if (threadIdx.x == 0) sig_s = sqrtf(vs / (float)(H_ - 1));
    __syncthreads();
    float inv = 1.f / (sig_s + LN_EPS_);
    for (int h = threadIdx.x; h < H_; h += blockDim.x) {
        gru_out[b * H_ + h] = (hn[h] - mu) * inv * la[h] + lb[h];
        hnew_out[b * H_ + h] = hn[h];
    }
}

// ---------------- copy-attention scores (reads gpart partial slices) ----------------
__global__ void k_zc(const float* __restrict__ zclin, const float* __restrict__ Pgp, int nsp,
                     const float* __restrict__ bc, const float* __restrict__ Wv1,
                     const float* __restrict__ bv1, float* __restrict__ zc)
{
    int tb = blockIdx.x;
    int t = tb / B_, b = tb % B_;
    float s = 0.f;
    for (int h = threadIdx.x; h < H_; h += blockDim.x) {
        float gp = 0.f;
        for (int sl = 0; sl < nsp; sl++)
            gp += Pgp[(size_t)sl * B_ * H_ + (size_t)b * H_ + h];
        s += Wv1[h] * tanhf(zclin[(size_t)tb * H_ + h] + gp + bc[h]);
    }
    s = blockSum(s);
    if (threadIdx.x == 0) zc[b * TZ_ + t] = s + bv1[0];
}

// ---------------- combine per-CTA softmax partials + zc ----------------
__global__ void k_stats(const float* __restrict__ pmax, const float* __restrict__ psum,
                        const float* __restrict__ zc,
                        float* __restrict__ mx, float* __restrict__ invs,
                        float* __restrict__ cp)
{
    int b = blockIdx.x, tid = threadIdx.x;
    int lane = tid & 31, wid = tid >> 5;
    float m = -1e30f, s = 0.f;
    for (int i = tid; i < GEN_CTAS; i += blockDim.x)
        osm(m, s, pmax[(size_t)i * B_ + b], psum[(size_t)i * B_ + b]);
    if (tid < TZ_) osm(m, s, zc[b * TZ_ + tid], 1.f);
    #pragma unroll
    for (int o = 16; o; o >>= 1) {
        float m2 = __shfl_xor_sync(0xffffffffu, m, o);
        float s2 = __shfl_xor_sync(0xffffffffu, s, o);
        osm(m, s, m2, s2);
    }
    __shared__ float shm[8], shs[8];
    __shared__ float fm, fs;
    if (lane == 0) { shm[wid] = m; shs[wid] = s; }
    __syncthreads();
    if (tid == 0) {
        float M = shm[0], S = shs[0];
        for (int w = 1; w < 8; w++) osm(M, S, shm[w], shs[w]);
        fm = M; fs = S;
        mx[b] = M; invs[b] = 1.f / S;
    }
    __syncthreads();
    if (tid < TZ_) cp[b * TZ_ + tid] = expf(zc[b * TZ_ + tid] - fm) / fs;
}

// ---------------- final: proba = gen_p + mask * (copy_p @ pz_proba), float4 ----------------
__global__ void k_write(const float* __restrict__ gen, const float* __restrict__ pz,
                        const float* __restrict__ mx, const float* __restrict__ invs,
                        const float* __restrict__ cp, float* __restrict__ out)
{
    int idx = blockIdx.x * blockDim.x + threadIdx.x;   // float4 index
    if (idx >= B_ * V_ / 4) return;
    int b = idx / (V_ / 4), v4 = idx % (V_ / 4);
    float4 g = ((const float4*)gen)[idx];
    float m = mx[b], inv = invs[b];
    float4 o;
    o.x = expf(g.x - m) * inv;
    o.y = expf(g.y - m) * inv;
    o.z = expf(g.z - m) * inv;
    o.w = expf(g.w - m) * inv;
    if (v4 >= FREQ_ / 4) {   // v >= 4 for all lanes of this float4
        float cx = 0.f, cy = 0.f, cz = 0.f, cw = 0.f;
        #pragma unroll
        for (int t = 0; t < TZ_; t++) {
            float w = cp[b * TZ_ + t];
            float4 p = ((const float4*)(pz + ((size_t)t * B_ + b) * V_))[v4];
            cx += w * p.x; cy += w * p.y; cz += w * p.z; cw += w * p.w;
        }
        o.x += cx; o.y += cy; o.z += cz; o.w += cw;
    }
    ((float4*)out)[idx] = o;
}

// ---------------- launch ----------------
extern "C" void kernel_launch(void* const* d_in, const int* in_sizes, int n_in,
                              void* d_out, int out_size)
{
    const float* z_enc  = (const float*)d_in[0];
    const float* pz     = (const float*)d_in[1];
    const float* u_enc  = (const float*)d_in[2];
    const int*   mt     = (const int*)  d_in[3];
    const float* hid    = (const float*)d_in[4];
    const float* emb    = (const float*)d_in[5];
    const float* Wa_z   = (const float*)d_in[6];
    const float* ba_z   = (const float*)d_in[7];
    const float* v_z    = (const float*)d_in[8];
    const float* Wa_u   = (const float*)d_in[9];
    const float* ba_u   = (const float*)d_in[10];
    const float* v_u    = (const float*)d_in[11];
    const float* W_ih   = (const float*)d_in[12];
    const float* W_hh   = (const float*)d_in[13];
    const float* b_ih   = (const float*)d_in[14];
    const float* b_hh   = (const float*)d_in[15];
    const float* ln_a   = (const float*)d_in[16];
    const float* ln_b   = (const float*)d_in[17];
    const float* W_proj = (const float*)d_in[18];
    const float* b_proj = (const float*)d_in[19];
    const float* W_c    = (const float*)d_in[20];
    const float* b_c    = (const float*)d_in[21];
    const float* W_v1   = (const float*)d_in[22];
    const float* b_v1   = (const float*)d_in[23];
    float* out = (float*)d_out;

    float* S;
    cudaGetSymbolAddress((void**)&S, g_scratch);
    float* scpU  = S + OFF_SCPU;
    float* scpZ  = S + OFF_SCPZ;
    float* PhpU  = S + OFF_PHPU;
    float* PhpZ  = S + OFF_PHPZ;
    float* x     = S + OFF_X;
    float* Pgi   = S + OFF_PGI;
    float* Pgh   = S + OFF_PGH;
    float* gru   = S + OFF_GRU;
    float* gen   = S + OFF_GEN;
    float* Pgp   = S + OFF_PGP;
    float* zclin = S + OFF_ZCLIN;
    float* zc    = S + OFF_ZC;
    float* mx    = S + OFF_MX;
    float* invs  = S + OFF_IS;
    float* cp    = S + OFF_CP;
    float* pmax  = S + OFF_PMAX;
    float* psum  = S + OFF_PSUM;
    const size_t SL3H = (size_t)B_ * 3 * H_;

    // ---------- fork ----------
    cudaEventRecord(g_evF, 0);
    cudaStreamWaitEvent(g_s1, g_evF, 0);
    cudaStreamWaitEvent(g_s2, g_evF, 0);
    cudaStreamWaitEvent(g_s3, g_evF, 0);

    // s0: hp_u (split8) -> Eu fused-score -> ctx_u -> gi_u (K chunk [H,2H), split2 -> slices 2,3)
    gemm_k<32,64,32,1,4,false,3,0><<<dim3(H_/64,1,8),128,SK_SMEM>>>(
        hid, Wa_u, nullptr, PhpU, B_, H_, H_, H_/8,
        nullptr,0,nullptr,nullptr,nullptr,nullptr,nullptr);
    gemm_k<128,128,32,2,4,false,3,1><<<dim3(H_/128, TU_*B_/128, 1),256,BIG_SMEM>>>(
        u_enc, Wa_u + (size_t)H_*H_, nullptr, nullptr, TU_*B_, H_, H_, H_,
        PhpU, 8, ba_u, v_u, scpU, nullptr, nullptr);
    k_softmax_ctx<<<dim3(B_, H_/256), 256>>>(scpU, H_/128, u_enc, x, TU_, H_);
    gemm_k<32,64,32,1,4,true,3,0><<<dim3(3*H_/64,1,2),128,SK_SMEM>>>(
        x + H_, W_ih + H_, nullptr, Pgi + 2*SL3H, B_, 3*H_, XD_, H_/2,
        nullptr,0,nullptr,nullptr,nullptr,nullptr,nullptr);

    // s1: hp_z (split8) -> Ez fused-score -> ctx_z -> gi_z (K chunk [0,H), split2 -> slices 0,1)
    gemm_k<32,64,32,1,4,false,3,0><<<dim3(H_/64,1,8),128,SK_SMEM,g_s1>>>(
        hid, Wa_z, nullptr, PhpZ, B_, H_, H_, H_/8,
        nullptr,0,nullptr,nullptr,nullptr,nullptr,nullptr);
    gemm_k<128,128,32,2,4,false,3,1><<<dim3(H_/128, TZ_*B_/128, 1),256,BIG_SMEM,g_s1>>>(
        z_enc, Wa_z + (size_t)H_*H_, nullptr, nullptr, TZ_*B_, H_, H_, H_,
        PhpZ, 8, ba_z, v_z, scpZ, nullptr, nullptr);
    k_softmax_ctx<<<dim3(B_, H_/256), 256, 0, g_s1>>>(scpZ, H_/128, z_enc, x, TZ_, 0);
    gemm_k<32,64,32,1,4,true,3,0><<<dim3(3*H_/64,1,2),128,SK_SMEM,g_s1>>>(
        x, W_ih, nullptr, Pgi, B_, 3*H_, XD_, H_/2,
        nullptr,0,nullptr,nullptr,nullptr,nullptr,nullptr);
    cudaEventRecord(g_e1, g_s1);

    // s2: emb -> gi_e (K chunk [2H,2H+E), slice 4) ; gh (split4)
    k_emb<<<B_, 128, 0, g_s2>>>(emb, mt, x);
    gemm_k<32,64,32,1,4,true,3,0><<<dim3(3*H_/64,1,1),128,SK_SMEM,g_s2>>>(
        x + 2*H_, W_ih + 2*H_, nullptr, Pgi + 4*SL3H, B_, 3*H_, XD_, E_,
        nullptr,0,nullptr,nullptr,nullptr,nullptr,nullptr);
    gemm_k<32,64,32,1,4,true,3,0><<<dim3(3*H_/64,1,4),128,SK_SMEM,g_s2>>>(
        hid, W_hh, nullptr, Pgh, B_, 3*H_, H_, H_/4,
        nullptr,0,nullptr,nullptr,nullptr,nullptr,nullptr);
    cudaEventRecord(g_e2, g_s2);

    // s3: zclin
    gemm_k<128,128,32,2,4,false,3,0><<<dim3(H_/128, TZ_*B_/128, 1),256,BIG_SMEM,g_s3>>>(
        z_enc, W_c, nullptr, zclin, TZ_*B_, H_, H_, H_,
        nullptr,0,nullptr,nullptr,nullptr,nullptr,nullptr);
    cudaEventRecord(g_e3, g_s3);

    // ---------- join for gru (gi slices 0-4 + gh slices) ----------
    cudaStreamWaitEvent(0, g_e1, 0);
    cudaStreamWaitEvent(0, g_e2, 0);
    k_gru_ln<<<B_, 256>>>(Pgi, 5, Pgh, 4, b_ih, b_hh, hid, ln_a, ln_b,
                          gru, out + (size_t)B_ * V_);

    // ---------- fork 2: copy path ∥ vocab GEMM ----------
    cudaEventRecord(g_eG, 0);
    cudaStreamWaitEvent(g_s1, g_eG, 0);
    cudaStreamWaitEvent(g_s1, g_e3, 0);
    gemm_k<32,64,32,1,4,false,3,0><<<dim3(H_/64,1,8),128,SK_SMEM,g_s1>>>(
        gru, W_c + (size_t)H_*H_, nullptr, Pgp, B_, H_, H_, H_/8,
        nullptr,0,nullptr,nullptr,nullptr,nullptr,nullptr);
    k_zc<<<TZ_ * B_, 256, 0, g_s1>>>(zclin, Pgp, 8, b_c, W_v1, b_v1, zc);
    cudaEventRecord(g_e4, g_s1);

    // s0: gen = gru @ W_proj + b_proj, with fused online-softmax partials
    gemm_k<32,64,32,1,4,false,3,2><<<dim3(V_/64,1,1),128,SK_SMEM>>>(
        gru, W_proj, b_proj, gen, B_, V_, H_, H_,
        nullptr,0,nullptr,nullptr,nullptr, pmax, psum);

    // ---------- join + final ----------
    cudaStreamWaitEvent(0, g_e4, 0);
    k_stats<<<B_, 256>>>(pmax, psum, zc, mx, invs, cp);
    k_write<<<(B_ * V_ / 4 + 255) / 256, 256>>>(gen, pz, mx, invs, cp, out);
}

// round 13
// speedup vs baseline: 1.1944x; 1.0208x over previous
#include <cuda_runtime.h>
#include <math.h>
#include <stdint.h>

#define B_  32
#define TZ_ 16
#define TU_ 128
#define E_  512
#define H_  1024
#define V_  32000
#define XD_ (E_ + 2*H_)     // 2560
#define LN_EPS_ 1e-3f
#define FREQ_ 4
#define GEN_CTAS (V_/64)    // 500

// ---------------- scratch (device global, no allocs) ----------------
#define OFF_SCPU   0                          // (TU*B) x 8 score partials (u)
#define OFF_SCPZ   (OFF_SCPU + TU_*B_*8)      // (TZ*B) x 8
#define OFF_PHPU   (OFF_SCPZ + TZ_*B_*8)      // 16 x B x H
#define OFF_PHPZ   (OFF_PHPU + 16*B_*H_)      // 16 x B x H
#define OFF_X      (OFF_PHPZ + 16*B_*H_)      // B x 2560
#define OFF_PGI    (OFF_X + B_*XD_)           // 10 x B x 3H
#define OFF_PGH    (OFF_PGI + 10*B_*3*H_)     // 8 x B x 3H
#define OFF_GRU    (OFF_PGH + 8*B_*3*H_)      // B x H
#define OFF_GEN    (OFF_GRU + B_*H_)          // B x V
#define OFF_CV     (OFF_GEN + B_*V_)          // B x V (unnormalized copy mixture)
#define OFF_PGP    (OFF_CV + B_*V_)           // 16 x B x H
#define OFF_ZCLIN  (OFF_PGP + 16*B_*H_)       // TZ*B x H
#define OFF_ZC     (OFF_ZCLIN + TZ_*B_*H_)    // B x TZ
#define OFF_UW     (OFF_ZC + B_*TZ_)          // B x TZ
#define OFF_LMZ    (OFF_UW + B_*TZ_)          // B
#define OFF_MX     (OFF_LMZ + B_)
#define OFF_IS     (OFF_MX + B_)
#define OFF_CW     (OFF_IS + B_)
#define OFF_PMAX   (OFF_CW + B_)              // GEN_CTAS x B
#define OFF_PSUM   (OFF_PMAX + GEN_CTAS*B_)
#define SCRATCH_TOTAL (OFF_PSUM + GEN_CTAS*B_)

__device__ float g_scratch[SCRATCH_TOTAL];

// ---------------- helpers ----------------
__device__ __forceinline__ uint32_t f2tf32u(float f) {
    uint32_t u;
    asm("cvt.rna.tf32.f32 %0, %1;" : "=r"(u) : "f"(f));
    return u;
}
__device__ __forceinline__ void cp16(void* smem, const void* gmem) {
    uint32_t s = (uint32_t)__cvta_generic_to_shared(smem);
    asm volatile("cp.async.ca.shared.global [%0], [%1], 16;" :: "r"(s), "l"(gmem));
}
__device__ __forceinline__ void cp_commit() { asm volatile("cp.async.commit_group;"); }
template<int N> __device__ __forceinline__ void cp_wait() {
    asm volatile("cp.async.wait_group %0;" :: "n"(N));
}

__device__ __forceinline__ float warpSum(float v) {
    #pragma unroll
    for (int o = 16; o; o >>= 1) v += __shfl_down_sync(0xffffffffu, v, o);
    return v;
}
__device__ float blockSum(float v) {
    __shared__ float sh[32];
    int lane = threadIdx.x & 31, wid = threadIdx.x >> 5;
    v = warpSum(v);
    if (lane == 0) sh[wid] = v;
    __syncthreads();
    v = (threadIdx.x < (blockDim.x >> 5)) ? sh[lane] : 0.f;
    if (wid == 0) v = warpSum(v);
    __syncthreads();
    return v;
}

// online softmax combine
__device__ __forceinline__ void osm(float& m, float& s, float m2, float s2) {
    float mn = fmaxf(m, m2);
    s = s * expf(m - mn) + s2 * expf(m2 - mn);
    m = mn;
}

// ---------------- tf32 tensor-core GEMM, multi-stage cp.async, BK=32 ----------------
// C[M,N] = A[M,K] @ op(B)   (K param is LDA/LDB; kLen per z-slice)
// TRANSB=false: B is KxN row-major; true: B is NxK (C = A@B^T)
// Split-K via grid.z (chunks of kLen; slice -> C + z*M*N)
// MODE 0: plain store (+bias if non-null)
// MODE 1: NO store; pre-reduce hp slices to smem; score partials
// MODE 2: store (+bias) AND per-CTA online-softmax partials pmax/psum (BM==32)
template<int BM,int BN,int BK,int WARPS_M,int WARPS_N,bool TRANSB,int STAGES,int MODE>
__global__ __launch_bounds__(32*WARPS_M*WARPS_N)
void gemm_k(const float* __restrict__ A, const float* __restrict__ Bm,
            const float* __restrict__ bias, float* __restrict__ C,
            int M, int N, int K, int kLen,
            const float* __restrict__ hpP, int hpS,
            const float* __restrict__ ba, const float* __restrict__ vv,
            float* __restrict__ scPart, float* __restrict__ pmax, float* __restrict__ psum)
{
    constexpr int NT  = 32 * WARPS_M * WARPS_N;
    constexpr int WM  = BM / WARPS_M;
    constexpr int WN  = BN / WARPS_N;
    constexpr int MT  = WM / 16;
    constexpr int NTL = WN / 8;
    constexpr int AST = BK + 4;
    constexpr int BROWS = TRANSB ? BN : BK;
    constexpr int BST   = TRANSB ? (BK + 4) : (BN + 8);

    extern __shared__ float sm_[];
    float* As_ = sm_;
    float* Bs_ = sm_ + STAGES * BM * AST;

    const int tid = threadIdx.x;
    const int wid = tid >> 5, lane = tid & 31;
    const int wm = wid / WARPS_N, wn = wid % WARPS_N;
    const int g = lane >> 2, tg = lane & 3;
    const int bm = blockIdx.y * BM, bn = blockIdx.x * BN;
    const int kStart = blockIdx.z * kLen;
    const int kTiles = kLen / BK;

    float acc[MT][NTL][4] = {};

    auto loadStage = [&](int s, int kb) {
        #pragma unroll
        for (int i = tid; i < BM * BK / 4; i += NT) {
            int r = i / (BK / 4), cq = i % (BK / 4);
            cp16(&As_[(s * BM + r) * AST + cq * 4],
                 &A[(size_t)(bm + r) * K + kStart + kb + cq * 4]);
        }
        if (!TRANSB) {
            #pragma unroll
            for (int i = tid; i < BK * BN / 4; i += NT) {
                int r = i / (BN / 4), cq = i % (BN / 4);
                cp16(&Bs_[(s * BROWS + r) * BST + cq * 4],
                     &Bm[(size_t)(kStart + kb + r) * N + bn + cq * 4]);
            }
        } else {
            #pragma unroll
            for (int i = tid; i < BN * BK / 4; i += NT) {
                int n = i / (BK / 4), cq = i % (BK / 4);
                cp16(&Bs_[(s * BROWS + n) * BST + cq * 4],
                     &Bm[(size_t)(bn + n) * K + kStart + kb + cq * 4]);
            }
        }
        cp_commit();
    };

    #pragma unroll
    for (int st = 0; st < STAGES - 1; st++) {
        if (st < kTiles) loadStage(st, st * BK); else cp_commit();
    }

    for (int kt = 0; kt < kTiles; kt++) {
        cp_wait<STAGES - 2>();
        __syncthreads();
        const int cur = kt % STAGES;
        const float* Asl = As_ + cur * BM * AST;
        const float* Bsl = Bs_ + cur * BROWS * BST;

        #pragma unroll
        for (int kk = 0; kk < BK; kk += 8) {
            uint32_t af[MT][4], bf[NTL][2];
            #pragma unroll
            for (int mt = 0; mt < MT; mt++) {
                int r0 = wm * WM + mt * 16 + g;
                af[mt][0] = f2tf32u(Asl[(r0    ) * AST + kk + tg    ]);
                af[mt][1] = f2tf32u(Asl[(r0 + 8) * AST + kk + tg    ]);
                af[mt][2] = f2tf32u(Asl[(r0    ) * AST + kk + tg + 4]);
                af[mt][3] = f2tf32u(Asl[(r0 + 8) * AST + kk + tg + 4]);
            }
            #pragma unroll
            for (int nt = 0; nt < NTL; nt++) {
                int c = wn * WN + nt * 8 + g;
                float b0 = TRANSB ? Bsl[c * BST + kk + tg    ] : Bsl[(kk + tg    ) * BST + c];
                float b1 = TRANSB ? Bsl[c * BST + kk + tg + 4] : Bsl[(kk + tg + 4) * BST + c];
                bf[nt][0] = f2tf32u(b0);
                bf[nt][1] = f2tf32u(b1);
            }
            #pragma unroll
            for (int mt = 0; mt < MT; mt++)
                #pragma unroll
                for (int nt = 0; nt < NTL; nt++) {
                    asm volatile(
                        "mma.sync.aligned.m16n8k8.row.col.f32.tf32.tf32.f32 "
                        "{%0,%1,%2,%3}, {%4,%5,%6,%7}, {%8,%9}, {%0,%1,%2,%3};\n"
                        : "+f"(acc[mt][nt][0]), "+f"(acc[mt][nt][1]),
                          "+f"(acc[mt][nt][2]), "+f"(acc[mt][nt][3])
                        : "r"(af[mt][0]), "r"(af[mt][1]), "r"(af[mt][2]), "r"(af[mt][3]),
                          "r"(bf[nt][0]), "r"(bf[nt][1]));
                }
        }
        __syncthreads();
        int nk = kt + STAGES - 1;
        if (nk < kTiles) loadStage(nk % STAGES, nk * BK); else cp_commit();
    }

    if constexpr (MODE == 0 || MODE == 2) {
        float* Cout = C + (size_t)blockIdx.z * M * N;
        float cv[MT][NTL][4];
        #pragma unroll
        for (int mt = 0; mt < MT; mt++) {
            int row0 = bm + wm * WM + mt * 16 + g;
            #pragma unroll
            for (int nt = 0; nt < NTL; nt++) {
                int col = bn + wn * WN + nt * 8 + 2 * tg;
                float bv0 = bias ? bias[col]     : 0.f;
                float bv1 = bias ? bias[col + 1] : 0.f;
                cv[mt][nt][0] = acc[mt][nt][0] + bv0;
                cv[mt][nt][1] = acc[mt][nt][1] + bv1;
                cv[mt][nt][2] = acc[mt][nt][2] + bv0;
                cv[mt][nt][3] = acc[mt][nt][3] + bv1;
                Cout[(size_t)row0 * N + col]           = cv[mt][nt][0];
                Cout[(size_t)row0 * N + col + 1]       = cv[mt][nt][1];
                Cout[(size_t)(row0 + 8) * N + col]     = cv[mt][nt][2];
                Cout[(size_t)(row0 + 8) * N + col + 1] = cv[mt][nt][3];
            }
        }
        if constexpr (MODE == 2) {
            __shared__ float smx[WARPS_N][32], ssm[WARPS_N][32], gmx[32];
            float lm[MT][2];
            #pragma unroll
            for (int mt = 0; mt < MT; mt++) {
                lm[mt][0] = -1e30f; lm[mt][1] = -1e30f;
                #pragma unroll
                for (int nt = 0; nt < NTL; nt++) {
                    lm[mt][0] = fmaxf(lm[mt][0], fmaxf(cv[mt][nt][0], cv[mt][nt][1]));
                    lm[mt][1] = fmaxf(lm[mt][1], fmaxf(cv[mt][nt][2], cv[mt][nt][3]));
                }
                #pragma unroll
                for (int h = 0; h < 2; h++) {
                    float m = lm[mt][h];
                    m = fmaxf(m, __shfl_xor_sync(0xffffffffu, m, 1));
                    m = fmaxf(m, __shfl_xor_sync(0xffffffffu, m, 2));
                    lm[mt][h] = m;
                    if (tg == 0) smx[wn][mt * 16 + h * 8 + g] = m;
                }
            }
            __syncthreads();
            if (tid < 32) {
                float m = smx[0][tid];
                #pragma unroll
                for (int w = 1; w < WARPS_N; w++) m = fmaxf(m, smx[w][tid]);
                gmx[tid] = m;
            }
            __syncthreads();
            #pragma unroll
            for (int mt = 0; mt < MT; mt++) {
                #pragma unroll
                for (int h = 0; h < 2; h++) {
                    int row = mt * 16 + h * 8 + g;
                    float m = gmx[row];
                    float s = 0.f;
                    #pragma unroll
                    for (int nt = 0; nt < NTL; nt++) {
                        s += expf(cv[mt][nt][2 * h]     - m);
                        s += expf(cv[mt][nt][2 * h + 1] - m);
                    }
                    s += __shfl_xor_sync(0xffffffffu, s, 1);
                    s += __shfl_xor_sync(0xffffffffu, s, 2);
                    if (tg == 0) ssm[wn][row] = s;
                }
            }
            __syncthreads();
            if (tid < 32) {
                float s = 0.f;
                #pragma unroll
                for (int w = 0; w < WARPS_N; w++) s += ssm[w][tid];
                pmax[(size_t)blockIdx.x * B_ + tid] = gmx[tid];
                psum[(size_t)blockIdx.x * B_ + tid] = s;
            }
        }
    }
    if constexpr (MODE == 1) {
        // pre-reduce hp slices into smem once per CTA
        __shared__ float hps[B_][BN + 4];
        for (int i = tid; i < B_ * BN; i += NT) {
            int b = i / BN, c = i % BN;
            float v = 0.f;
            for (int sl = 0; sl < hpS; sl++)
                v += hpP[(size_t)sl * B_ * H_ + (size_t)b * H_ + bn + c];
            hps[b][c] = v;
        }
        __shared__ float sred[WARPS_N][BM];
        __syncthreads();
        #pragma unroll
        for (int mt = 0; mt < MT; mt++) {
            int rloc0 = wm * WM + mt * 16 + g;
            #pragma unroll
            for (int h = 0; h < 2; h++) {
                int rloc = rloc0 + h * 8;
                int b = (bm + rloc) & (B_ - 1);
                float s = 0.f;
                #pragma unroll
                for (int nt = 0; nt < NTL; nt++) {
                    #pragma unroll
                    for (int j = 0; j < 2; j++) {
                        int cl = wn * WN + nt * 8 + 2 * tg + j;
                        float e = tanhf(acc[mt][nt][2 * h + j] + hps[b][cl] + ba[bn + cl]);
                        s += e * vv[bn + cl];
                    }
                }
                s += __shfl_xor_sync(0xffffffffu, s, 1);
                s += __shfl_xor_sync(0xffffffffu, s, 2);
                if (tg == 0) sred[wn][rloc] = s;
            }
        }
        __syncthreads();
        if (tid < BM) {
            float s = 0.f;
            #pragma unroll
            for (int w = 0; w < WARPS_N; w++) s += sred[w][tid];
            scPart[(size_t)(bm + tid) * gridDim.x + blockIdx.x] = s;
        }
    }
}

// dynamic smem sizes (BK=32, 3 stages)
#define BIG_SMEM  ((3*128*36 + 3*32*136) * 4)          // 107520
#define SK_SMEM   ((3*32*36 + 3*64*36) * 4)            // 41472

// ---------------- streams & events ----------------
static cudaStream_t g_s1, g_s2, g_s3;
static cudaEvent_t  g_evF, g_e1, g_e2, g_e3, g_eG, g_e4;
namespace {
struct SInit {
    SInit() {
        cudaStreamCreateWithFlags(&g_s1, cudaStreamNonBlocking);
        cudaStreamCreateWithFlags(&g_s2, cudaStreamNonBlocking);
        cudaStreamCreateWithFlags(&g_s3, cudaStreamNonBlocking);
        cudaEventCreateWithFlags(&g_evF, cudaEventDisableTiming);
        cudaEventCreateWithFlags(&g_e1,  cudaEventDisableTiming);
        cudaEventCreateWithFlags(&g_e2,  cudaEventDisableTiming);
        cudaEventCreateWithFlags(&g_e3,  cudaEventDisableTiming);
        cudaEventCreateWithFlags(&g_eG,  cudaEventDisableTiming);
        cudaEventCreateWithFlags(&g_e4,  cudaEventDisableTiming);
        cudaFuncSetAttribute((const void*)gemm_k<128,128,32,2,4,false,3,0>,
                             cudaFuncAttributeMaxDynamicSharedMemorySize, BIG_SMEM);
        cudaFuncSetAttribute((const void*)gemm_k<128,128,32,2,4,false,3,1>,
                             cudaFuncAttributeMaxDynamicSharedMemorySize, BIG_SMEM);
    }
};
SInit g_sinit;
}

// ---------------- embedding gather into x[:, 2H:2H+E] ----------------
__global__ void k_emb(const float* __restrict__ emb, const int* __restrict__ mt,
                      float* __restrict__ x)
{
    int b = blockIdx.x;
    int tok = mt[b];
    for (int e = threadIdx.x; e < E_; e += blockDim.x)
        x[b * XD_ + 2 * H_ + e] = emb[(size_t)tok * E_ + e];
}

// ---------------- softmax over t (from score partials) + context ----------------
__global__ void k_softmax_ctx(const float* __restrict__ scPart, int GX,
                              const float* __restrict__ enc,
                              float* __restrict__ x, int T, int xoff)
{
    int b = blockIdx.x;
    int h = blockIdx.y * 256 + threadIdx.x;
    int tid = threadIdx.x, lane = tid & 31, wid = tid >> 5;
    __shared__ float w[TU_];
    __shared__ float red[8];
    __shared__ float bval;
    float val = -1e30f;
    if (tid < T) {
        float s = 0.f;
        for (int gx = 0; gx < GX; gx++)
            s += scPart[(size_t)(tid * B_ + b) * GX + gx];
        w[tid] = s;
        val = s;
    }
    float m = val;
    #pragma unroll
    for (int o = 16; o; o >>= 1) m = fmaxf(m, __shfl_xor_sync(0xffffffffu, m, o));
    if (lane == 0) red[wid] = m;
    __syncthreads();
    if (tid == 0) {
        float mm = red[0];
        for (int i = 1; i < 8; i++) mm = fmaxf(mm, red[i]);
        bval = mm;
    }
    __syncthreads();
    float gmax = bval;
    float e = (tid < T) ? expf(w[tid] - gmax) : 0.f;
    float s = e;
    #pragma unroll
    for (int o = 16; o; o >>= 1) s += __shfl_xor_sync(0xffffffffu, s, o);
    if (lane == 0) red[wid] = s;
    __syncthreads();
    if (tid == 0) {
        float ss = 0.f;
        for (int i = 0; i < 8; i++) ss += red[i];
        bval = 1.f / ss;
    }
    __syncthreads();
    if (tid < T) w[tid] = e * bval;
    __syncthreads();
    float acc = 0.f;
    for (int t = 0; t < T; t++)
        acc += w[t] * enc[((size_t)t * B_ + b) * H_ + h];
    x[b * XD_ + xoff + h] = acc;
}

// ---------------- GRU cell + layernorm, reads split-K partial slices ----------------
__global__ void k_gru_ln(const float* __restrict__ Pgi, int nsi,
                         const float* __restrict__ Pgh, int nsh,
                         const float* __restrict__ b_ih, const float* __restrict__ b_hh,
                         const float* __restrict__ hprev,
                         const float* __restrict__ la, const float* __restrict__ lb,
                         float* __restrict__ gru_out, float* __restrict__ hnew_out)
{
    int b = blockIdx.x;
    __shared__ float hn[H_];
    __shared__ float mu_s, sig_s;
    const size_t SL = (size_t)B_ * 3 * H_;
    for (int h = threadIdx.x; h < H_; h += blockDim.x) {
        float ir = b_ih[h], iz = b_ih[H_ + h], in = b_ih[2 * H_ + h];
        for (int s = 0; s < nsi; s++) {
            const float* p = Pgi + s * SL + (size_t)b * 3 * H_;
            ir += p[h]; iz += p[H_ + h]; in += p[2 * H_ + h];
        }
        float hr = b_hh[h], hz = b_hh[H_ + h], hnn = b_hh[2 * H_ + h];
        for (int s = 0; s < nsh; s++) {
            const float* p = Pgh + s * SL + (size_t)b * 3 * H_;
            hr += p[h]; hz += p[H_ + h]; hnn += p[2 * H_ + h];
        }
        float r  = 1.f / (1.f + expf(-(ir + hr)));
        float zg = 1.f / (1.f + expf(-(iz + hz)));
        float n  = tanhf(in + r * hnn);
        float hp = hprev[b * H_ + h];
        hn[h] = (1.f - zg) * n + zg * hp;
    }
    __syncthreads();
    float s = 0.f;
    for (int h = threadIdx.x; h < H_; h += blockDim.x) s += hn[h];
    s = blockSum(s);
    if (threadIdx.x == 0) mu_s = s / H_;
    __syncthreads();
    float mu = mu_s;
    float vs = 0.f;
    for (int h = threadIdx.x; h < H_; h += blockDim.x) { float d = hn[h] - mu; vs += d * d; }
    vs = blockSum(vs);
    if (threadIdx.x == 0) sig_s = sqrtf(vs / (float)(H_ - 1));
    __syncthreads();
    float inv = 1.f / (sig_s + LN_EPS_);
    for (int h = threadIdx.x; h < H_; h += blockDim.x) {
        gru_out[b * H_ + h] = (hn[h] - mu) * inv * la[h] + lb[h];
        hnew_out[b * H_ + h] = hn[h];
    }
}

// ---------------- copy-attention scores (reads gpart partial slices) ----------------
__global__ void k_zc(const float* __restrict__ zclin, const float* __restrict__ Pgp, int nsp,
                     const float* __restrict__ bc, const float* __restrict__ Wv1,
                     const float* __restrict__ bv1, float* __restrict__ zc)
{
    int tb = blockIdx.x;
    int t = tb / B_, b = tb % B_;
    float s = 0.f;
    for (int h = threadIdx.x; h < H_; h += blockDim.x) {
        float gp = 0.f;
        for (int sl = 0; sl < nsp; sl++)
            gp += Pgp[(size_t)sl * B_ * H_ + (size_t)b * H_ + h];
        s += Wv1[h] * tanhf(zclin[(size_t)tb * H_ + h] + gp + bc[h]);
    }
    s = blockSum(s);
    if (threadIdx.x == 0) zc[b * TZ_ + t] = s + bv1[0];
}

// ---------------- per-b local max + unnormalized copy weights ----------------
__global__ void k_uw(const float* __restrict__ zc, float* __restrict__ uw,
                     float* __restrict__ lmz)
{
    int b = threadIdx.x;
    if (b < B_) {
        float m = -1e30f;
        #pragma unroll
        for (int t = 0; t < TZ_; t++) m = fmaxf(m, zc[b * TZ_ + t]);
        lmz[b] = m;
        #pragma unroll
        for (int t = 0; t < TZ_; t++) uw[b * TZ_ + t] = expf(zc[b * TZ_ + t] - m);
    }
}

// ---------------- unnormalized copy mixture: cv = sum_t uw[t] * pz[t]  (runs ∥ gen) ----
__global__ void k_copy(const float* __restrict__ uw, const float* __restrict__ pz,
                       float* __restrict__ cv)
{
    int idx = blockIdx.x * blockDim.x + threadIdx.x;   // float4 index
    if (idx >= B_ * V_ / 4) return;
    int b = idx / (V_ / 4), v4 = idx % (V_ / 4);
    float cx = 0.f, cy = 0.f, cz = 0.f, cw = 0.f;
    #pragma unroll
    for (int t = 0; t < TZ_; t++) {
        float w = uw[b * TZ_ + t];
        float4 p = ((const float4*)(pz + ((size_t)t * B_ + b) * V_))[v4];
        cx += w * p.x; cy += w * p.y; cz += w * p.z; cw += w * p.w;
    }
    float4 o; o.x = cx; o.y = cy; o.z = cz; o.w = cw;
    ((float4*)cv)[idx] = o;
}

// ---------------- combine per-CTA softmax partials + zc ----------------
__global__ void k_stats(const float* __restrict__ pmax, const float* __restrict__ psum,
                        const float* __restrict__ zc, const float* __restrict__ lmz,
                        float* __restrict__ mx, float* __restrict__ invs,
                        float* __restrict__ cwv)
{
    int b = blockIdx.x, tid = threadIdx.x;
    int lane = tid & 31, wid = tid >> 5;
    float m = -1e30f, s = 0.f;
    for (int i = tid; i < GEN_CTAS; i += blockDim.x)
        osm(m, s, pmax[(size_t)i * B_ + b], psum[(size_t)i * B_ + b]);
    if (tid < TZ_) osm(m, s, zc[b * TZ_ + tid], 1.f);
    #pragma unroll
    for (int o = 16; o; o >>= 1) {
        float m2 = __shfl_xor_sync(0xffffffffu, m, o);
        float s2 = __shfl_xor_sync(0xffffffffu, s, o);
        osm(m, s, m2, s2);
    }
    __shared__ float shm[8], shs[8];
    if (lane == 0) { shm[wid] = m; shs[wid] = s; }
    __syncthreads();
    if (tid == 0) {
        float M = shm[0], S = shs[0];
        for (int w = 1; w < 8; w++) osm(M, S, shm[w], shs[w]);
        mx[b] = M;
        invs[b] = 1.f / S;
        cwv[b] = expf(lmz[b] - M) / S;
    }
}

// ---------------- final: proba = e^(gen-M)/S + mask * cw * cv, float4 ----------------
__global__ void k_write(const float* __restrict__ gen, const float* __restrict__ cv,
                        const float* __restrict__ mx, const float* __restrict__ invs,
                        const float* __restrict__ cwv, float* __restrict__ out)
{
    int idx = blockIdx.x * blockDim.x + threadIdx.x;   // float4 index
    if (idx >= B_ * V_ / 4) return;
    int b = idx / (V_ / 4), v4 = idx % (V_ / 4);
    float4 g = ((const float4*)gen)[idx];
    float m = mx[b], inv = invs[b];
    float4 o;
    o.x = expf(g.x - m) * inv;
    o.y = expf(g.y - m) * inv;
    o.z = expf(g.z - m) * inv;
    o.w = expf(g.w - m) * inv;
    if (v4 >= FREQ_ / 4) {
        float w = cwv[b];
        float4 c = ((const float4*)cv)[idx];
        o.x += w * c.x; o.y += w * c.y; o.z += w * c.z; o.w += w * c.w;
    }
    ((float4*)out)[idx] = o;
}

// ---------------- launch ----------------
extern "C" void kernel_launch(void* const* d_in, const int* in_sizes, int n_in,
                              void* d_out, int out_size)
{
    const float* z_enc  = (const float*)d_in[0];
    const float* pz     = (const float*)d_in[1];
    const float* u_enc  = (const float*)d_in[2];
    const int*   mt     = (const int*)  d_in[3];
    const float* hid    = (const float*)d_in[4];
    const float* emb    = (const float*)d_in[5];
    const float* Wa_z   = (const float*)d_in[6];
    const float* ba_z   = (const float*)d_in[7];
    const float* v_z    = (const float*)d_in[8];
    const float* Wa_u   = (const float*)d_in[9];
    const float* ba_u   = (const float*)d_in[10];
    const float* v_u    = (const float*)d_in[11];
    const float* W_ih   = (const float*)d_in[12];
    const float* W_hh   = (const float*)d_in[13];
    const float* b_ih   = (const float*)d_in[14];
    const float* b_hh   = (const float*)d_in[15];
    const float* ln_a   = (const float*)d_in[16];
    const float* ln_b   = (const float*)d_in[17];
    const float* W_proj = (const float*)d_in[18];
    const float* b_proj = (const float*)d_in[19];
    const float* W_c    = (const float*)d_in[20];
    const float* b_c    = (const float*)d_in[21];
    const float* W_v1   = (const float*)d_in[22];
    const float* b_v1   = (const float*)d_in[23];
    float* out = (float*)d_out;

    float* S;
    cudaGetSymbolAddress((void**)&S, g_scratch);
    float* scpU  = S + OFF_SCPU;
    float* scpZ  = S + OFF_SCPZ;
    float* PhpU  = S + OFF_PHPU;
    float* PhpZ  = S + OFF_PHPZ;
    float* x     = S + OFF_X;
    float* Pgi   = S + OFF_PGI;
    float* Pgh   = S + OFF_PGH;
    float* gru   = S + OFF_GRU;
    float* gen   = S + OFF_GEN;
    float* cv    = S + OFF_CV;
    float* Pgp   = S + OFF_PGP;
    float* zclin = S + OFF_ZCLIN;
    float* zc    = S + OFF_ZC;
    float* uw    = S + OFF_UW;
    float* lmz   = S + OFF_LMZ;
    float* mx    = S + OFF_MX;
    float* invs  = S + OFF_IS;
    float* cwv   = S + OFF_CW;
    float* pmax  = S + OFF_PMAX;
    float* psum  = S + OFF_PSUM;
    const size_t SL3H = (size_t)B_ * 3 * H_;

    // ---------- fork ----------
    cudaEventRecord(g_evF, 0);
    cudaStreamWaitEvent(g_s1, g_evF, 0);
    cudaStreamWaitEvent(g_s2, g_evF, 0);
    cudaStreamWaitEvent(g_s3, g_evF, 0);

    // s0: hp_u (split16) -> Eu fused-score -> ctx_u -> gi_u (K [H,2H), split4 -> slices 4-7)
    gemm_k<32,64,32,1,4,false,3,0><<<dim3(H_/64,1,16),128,SK_SMEM>>>(
        hid, Wa_u, nullptr, PhpU, B_, H_, H_, H_/16,
        nullptr,0,nullptr,nullptr,nullptr,nullptr,nullptr);
    gemm_k<128,128,32,2,4,false,3,1><<<dim3(H_/128, TU_*B_/128, 1),256,BIG_SMEM>>>(
        u_enc, Wa_u + (size_t)H_*H_, nullptr, nullptr, TU_*B_, H_, H_, H_,
        PhpU, 16, ba_u, v_u, scpU, nullptr, nullptr);
    k_softmax_ctx<<<dim3(B_, H_/256), 256>>>(scpU, H_/128, u_enc, x, TU_, H_);
    gemm_k<32,64,32,1,4,true,3,0><<<dim3(3*H_/64,1,4),128,SK_SMEM>>>(
        x + H_, W_ih + H_, nullptr, Pgi + 4*SL3H, B_, 3*H_, XD_, H_/4,
        nullptr,0,nullptr,nullptr,nullptr,nullptr,nullptr);

    // s1: hp_z (split16) -> Ez fused-score -> ctx_z -> gi_z (K [0,H), split4 -> slices 0-3)
    gemm_k<32,64,32,1,4,false,3,0><<<dim3(H_/64,1,16),128,SK_SMEM,g_s1>>>(
        hid, Wa_z, nullptr, PhpZ, B_, H_, H_, H_/16,
        nullptr,0,nullptr,nullptr,nullptr,nullptr,nullptr);
    gemm_k<128,128,32,2,4,false,3,1><<<dim3(H_/128, TZ_*B_/128, 1),256,BIG_SMEM,g_s1>>>(
        z_enc, Wa_z + (size_t)H_*H_, nullptr, nullptr, TZ_*B_, H_, H_, H_,
        PhpZ, 16, ba_z, v_z, scpZ, nullptr, nullptr);
    k_softmax_ctx<<<dim3(B_, H_/256), 256, 0, g_s1>>>(scpZ, H_/128, z_enc, x, TZ_, 0);
    gemm_k<32,64,32,1,4,true,3,0><<<dim3(3*H_/64,1,4),128,SK_SMEM,g_s1>>>(
        x, W_ih, nullptr, Pgi, B_, 3*H_, XD_, H_/4,
        nullptr,0,nullptr,nullptr,nullptr,nullptr,nullptr);
    cudaEventRecord(g_e1, g_s1);

    // s2: emb -> gi_e (K [2H,2H+E), split2 -> slices 8,9) ; gh (split8)
    k_emb<<<B_, 128, 0, g_s2>>>(emb, mt, x);
    gemm_k<32,64,32,1,4,true,3,0><<<dim3(3*H_/64,1,2),128,SK_SMEM,g_s2>>>(
        x + 2*H_, W_ih + 2*H_, nullptr, Pgi + 8*SL3H, B_, 3*H_, XD_, E_/2,
        nullptr,0,nullptr,nullptr,nullptr,nullptr,nullptr);
    gemm_k<32,64,32,1,4,true,3,0><<<dim3(3*H_/64,1,8),128,SK_SMEM,g_s2>>>(
        hid, W_hh, nullptr, Pgh, B_, 3*H_, H_, H_/8,
        nullptr,0,nullptr,nullptr,nullptr,nullptr,nullptr);
    cudaEventRecord(g_e2, g_s2);

    // s3: zclin
    gemm_k<128,128,32,2,4,false,3,0><<<dim3(H_/128, TZ_*B_/128, 1),256,BIG_SMEM,g_s3>>>(
        z_enc, W_c, nullptr, zclin, TZ_*B_, H_, H_, H_,
        nullptr,0,nullptr,nullptr,nullptr,nullptr,nullptr);
    cudaEventRecord(g_e3, g_s3);

    // ---------- join for gru (gi slices 0-9 + gh slices 0-7) ----------
    cudaStreamWaitEvent(0, g_e1, 0);
    cudaStreamWaitEvent(0, g_e2, 0);
    k_gru_ln<<<B_, 256>>>(Pgi, 10, Pgh, 8, b_ih, b_hh, hid, ln_a, ln_b,
                          gru, out + (size_t)B_ * V_);

    // ---------- fork 2: copy path (gpart, zc, uw, copy-mixture) ∥ vocab GEMM ----------
    cudaEventRecord(g_eG, 0);
    cudaStreamWaitEvent(g_s1, g_eG, 0);
    cudaStreamWaitEvent(g_s1, g_e3, 0);
    gemm_k<32,64,32,1,4,false,3,0><<<dim3(H_/64,1,16),128,SK_SMEM,g_s1>>>(
        gru, W_c + (size_t)H_*H_, nullptr, Pgp, B_, H_, H_, H_/16,
        nullptr,0,nullptr,nullptr,nullptr,nullptr,nullptr);
    k_zc<<<TZ_ * B_, 256, 0, g_s1>>>(zclin, Pgp, 16, b_c, W_v1, b_v1, zc);
    k_uw<<<1, 32, 0, g_s1>>>(zc, uw, lmz);
    k_copy<<<(B_ * V_ / 4 + 255) / 256, 256, 0, g_s1>>>(uw, pz, cv);
    cudaEventRecord(g_e4, g_s1);

    // s0: gen = gru @ W_proj + b_proj, with fused online-softmax partials
    gemm_k<32,64,32,1,4,false,3,2><<<dim3(V_/64,1,1),128,SK_SMEM>>>(
        gru, W_proj, b_proj, gen, B_, V_, H_, H_,
        nullptr,0,nullptr,nullptr,nullptr, pmax, psum);

    // ---------- join + final ----------
    cudaStreamWaitEvent(0, g_e4, 0);
    k_stats<<<B_, 256>>>(pmax, psum, zc, lmz, mx, invs, cwv);
    k_write<<<(B_ * V_ / 4 + 255) / 256, 256>>>(gen, cv, mx, invs, cwv, out);
}